// round 13
// baseline (speedup 1.0000x reference)
#include <cuda_runtime.h>
#include <cuda_bf16.h>
#include <cstdint>

#define NLEV 4
#define KCB  256
#define DIM  128
#define ROWS 128                 // two 64-row halves per block
#define TPB  256
#define PAD  136                 // bf16 halves per padded tile row (conflict-free ldmatrix)
#define RPAD 132                 // floats per padded residual row (conflict-free verify)
#define EPRUNE 0.5f

// ---------------- global scratch (allocation-free rule) ----------------
__device__ unsigned short g_cbH[NLEV * KCB * PAD];   // bf16(hi) codebook, padded rows
__device__ float g_cnorm[NLEV * KCB];

// ---------------- prep: bf16 codebook + norms ----------------
__global__ void rq_prep_kernel(const float* __restrict__ cb) {
    int i = blockIdx.x * blockDim.x + threadIdx.x;
    const int total = NLEV * KCB * DIM;
    if (i < total) {
        int l = i / (KCB * DIM);
        int rem = i - l * (KCB * DIM);
        int e = rem >> 7, k = rem & 127;
        g_cbH[(l * KCB + e) * PAD + k] =
            __bfloat16_as_ushort(__float2bfloat16(cb[i]));
    }
    if (i < NLEV * KCB) {
        const float* p = cb + (size_t)i * DIM;
        float s = 0.0f;
        #pragma unroll 1
        for (int k = 0; k < DIM; k++) s = fmaf(p[k], p[k], s);
        g_cnorm[i] = s;
    }
}

// ---------------- PTX helpers (all baseline sm_80+, no 'a' features) ----------------
__device__ __forceinline__ uint32_t smem_u32(const void* p) {
    uint32_t a;
    asm("{ .reg .u64 t; cvta.to.shared.u64 t, %1; cvt.u32.u64 %0, t; }" : "=r"(a) : "l"(p));
    return a;
}
__device__ __forceinline__ void cp16(uint32_t s, const void* g) {
    asm volatile("cp.async.cg.shared.global [%0], [%1], 16;" :: "r"(s), "l"(g));
}
__device__ __forceinline__ void ldsm_x4(uint32_t& r0, uint32_t& r1, uint32_t& r2, uint32_t& r3,
                                        uint32_t addr) {
    asm volatile("ldmatrix.sync.aligned.m8n8.x4.shared.b16 {%0,%1,%2,%3}, [%4];"
                 : "=r"(r0), "=r"(r1), "=r"(r2), "=r"(r3) : "r"(addr));
}
__device__ __forceinline__ void mma16816(float* d,
                                         uint32_t a0, uint32_t a1, uint32_t a2, uint32_t a3,
                                         uint32_t b0, uint32_t b1) {
    asm volatile("mma.sync.aligned.m16n8k16.row.col.f32.bf16.bf16.f32 "
                 "{%0,%1,%2,%3}, {%4,%5,%6,%7}, {%8,%9}, {%0,%1,%2,%3};"
                 : "+f"(d[0]), "+f"(d[1]), "+f"(d[2]), "+f"(d[3])
                 : "r"(a0), "r"(a1), "r"(a2), "r"(a3), "r"(b0), "r"(b1));
}

// exact fp32 distance (sequential-k fmaf — same arithmetic as the R4-R8 kernels)
__device__ __forceinline__ float exact_dist(const float* resRow, const float* cbRow, float cn) {
    float s = 0.0f;
    #pragma unroll
    for (int k4 = 0; k4 < 32; k4++) {
        float4 c = __ldg((const float4*)cbRow + k4);
        float4 r = ((const float4*)resRow)[k4];
        s = fmaf(r.x, c.x, s); s = fmaf(r.y, c.y, s);
        s = fmaf(r.z, c.z, s); s = fmaf(r.w, c.w, s);
    }
    return fmaf(-2.0f, s, cn);
}

// ---------------- smem layout (bytes) ----------------
#define SM_B     0                      // 256*136*2          = 69632
#define SM_AHI   69632                  // 64*136*2           = 17408
#define SM_ALO   87040                  // 17408
#define SM_RES   104448                 // 128*132*4          = 67584
#define SM_CN    172032                 // 4096
#define SM_BESTD 176128                 // 64*4
#define SM_EXD   176384                 // 64*4
#define SM_EXI   176640                 // 64*4
#define SM_TOTAL 176896

extern __shared__ __align__(16) char smem[];

__global__ void __launch_bounds__(TPB)
rq_main_kernel(const float* __restrict__ x,
               const float* __restrict__ cb,
               float* __restrict__ out_recon,
               float* __restrict__ out_codes,
               int write_codes) {
    const int tid    = threadIdx.x;
    const int lane   = tid & 31;
    const int wid    = tid >> 5;
    const int warp_m = wid & 3;          // row group (16 rows) within 64-row half
    const int warp_n = wid >> 2;         // entry half (128 entries)
    const long long row0 = (long long)blockIdx.x * ROWS;
    const uint32_t sbase = smem_u32(smem);

    float* resF  = (float*)(smem + SM_RES);
    float* shCn  = (float*)(smem + SM_CN);
    float* bestd = (float*)(smem + SM_BESTD);
    float* exd   = (float*)(smem + SM_EXD);
    int*   exi   = (int*)  (smem + SM_EXI);

    // cnorms -> smem (1024 floats)
    ((float4*)shCn)[tid] = ((const float4*)g_cnorm)[tid];

    // x tile -> padded fp32 residual
    const float4* x4 = (const float4*)(x + row0 * DIM);
    #pragma unroll
    for (int i = 0; i < 16; i++) {
        int idx = tid + i * TPB;         // over 128*32 float4
        int row = idx >> 5, c4 = idx & 31;
        ((float4*)(resF + row * RPAD))[c4] = x4[idx];
    }

    // stage level-0 B (bf16-hi codebook, pre-padded -> linear 69632B copy)
    {
        const char* gsrc = (const char*)g_cbH;
        #pragma unroll
        for (int i = 0; i < 17; i++)
            cp16(sbase + SM_B + (tid + i * TPB) * 16, gsrc + (size_t)(tid + i * TPB) * 16);
        asm volatile("cp.async.commit_group;");
    }

    // ldmatrix address components (constant across levels)
    const int arow = warp_m * 16 + (lane & 15);
    const uint32_t aoff = (uint32_t)(arow * PAD + ((lane >> 4) << 3)) * 2;
    const int bErow = warp_n * 128 + ((lane >> 4) << 3) + (lane & 7);
    const uint32_t bko  = (uint32_t)(((lane >> 3) & 1) << 3);
    const int rloc = warp_m * 16 + (lane >> 2);      // epilogue row (plus +8)

    for (int l = 0; l < NLEV; l++) {
        asm volatile("cp.async.wait_group 0;" ::: "memory");
        __syncthreads();
        const float* cnl = shCn + l * KCB;

        #pragma unroll 1
        for (int half = 0; half < 2; half++) {
            // ---- convert this half's residual rows to bf16 hi/lo A tiles ----
            #pragma unroll 4
            for (int i = 0; i < 16; i++) {
                int idx = tid + i * TPB;             // 64*64 float2 pairs
                int row = idx >> 6;
                int kp  = (idx & 63) * 2;
                float2 v = *(const float2*)(resF + (half * 64 + row) * RPAD + kp);
                __nv_bfloat16 h0 = __float2bfloat16(v.x);
                __nv_bfloat16 h1 = __float2bfloat16(v.y);
                __nv_bfloat16 l0 = __float2bfloat16(v.x - __bfloat162float(h0));
                __nv_bfloat16 l1 = __float2bfloat16(v.y - __bfloat162float(h1));
                *(uint32_t*)(smem + SM_AHI + (row * PAD + kp) * 2) =
                    ((uint32_t)__bfloat16_as_ushort(h1) << 16) | __bfloat16_as_ushort(h0);
                *(uint32_t*)(smem + SM_ALO + (row * PAD + kp) * 2) =
                    ((uint32_t)__bfloat16_as_ushort(l1) << 16) | __bfloat16_as_ushort(l0);
            }
            __syncthreads();

            // ---- GEMM: acc[nt][..] = dot(r, c_hi) for 16 rows x 128 entries/warp ----
            float acc[16][4];
            #pragma unroll
            for (int nt = 0; nt < 16; nt++) {
                acc[nt][0] = 0.f; acc[nt][1] = 0.f; acc[nt][2] = 0.f; acc[nt][3] = 0.f;
            }
            const uint32_t Ah = sbase + SM_AHI + aoff;
            const uint32_t Al = sbase + SM_ALO + aoff;
            const uint32_t Bb = sbase + SM_B + (uint32_t)(bErow * PAD + bko) * 2;
            #pragma unroll
            for (int ks = 0; ks < 8; ks++) {
                uint32_t h0, h1, h2, h3, l0, l1, l2, l3;
                ldsm_x4(h0, h1, h2, h3, Ah + ks * 32);
                ldsm_x4(l0, l1, l2, l3, Al + ks * 32);
                #pragma unroll
                for (int nt = 0; nt < 16; nt += 2) {
                    uint32_t b0, b1, b2, b3;
                    ldsm_x4(b0, b1, b2, b3, Bb + (uint32_t)(nt * 8 * PAD + ks * 16) * 2);
                    mma16816(acc[nt],     h0, h1, h2, h3, b0, b1);
                    mma16816(acc[nt],     l0, l1, l2, l3, b0, b1);
                    mma16816(acc[nt + 1], h0, h1, h2, h3, b2, b3);
                    mma16816(acc[nt + 1], l0, l1, l2, l3, b2, b3);
                }
            }

            // ---- pass 1: approx per-row min (value only -> threshold) ----
            const int cbase = warp_n * 128 + (lane & 3) * 2;
            float m0 = 3.402823466e38f, m1 = 3.402823466e38f;
            #pragma unroll
            for (int nt = 0; nt < 16; nt++) {
                int c = cbase + nt * 8;
                float cn0 = cnl[c], cn1 = cnl[c + 1];
                m0 = fminf(m0, fmaf(-2.f, acc[nt][0], cn0));
                m0 = fminf(m0, fmaf(-2.f, acc[nt][1], cn1));
                m1 = fminf(m1, fmaf(-2.f, acc[nt][2], cn0));
                m1 = fminf(m1, fmaf(-2.f, acc[nt][3], cn1));
            }
            m0 = fminf(m0, __shfl_xor_sync(0xffffffffu, m0, 1));
            m0 = fminf(m0, __shfl_xor_sync(0xffffffffu, m0, 2));
            m1 = fminf(m1, __shfl_xor_sync(0xffffffffu, m1, 1));
            m1 = fminf(m1, __shfl_xor_sync(0xffffffffu, m1, 2));
            if (warp_n == 0 && (lane & 3) == 0) { bestd[rloc] = m0; bestd[rloc + 8] = m1; }
            __syncthreads();
            if (warp_n == 1 && (lane & 3) == 0) {
                if (m0 < bestd[rloc])     bestd[rloc]     = m0;
                if (m1 < bestd[rloc + 8]) bestd[rloc + 8] = m1;
            }
            // overlap: prefetch next level's B during the rest of the epilogue
            if (half == 1) {
                __syncthreads();
                if (l + 1 < NLEV) {
                    const char* gsrc = (const char*)g_cbH + (size_t)(l + 1) * KCB * PAD * 2;
                    #pragma unroll
                    for (int i = 0; i < 17; i++)
                        cp16(sbase + SM_B + (tid + i * TPB) * 16,
                             gsrc + (size_t)(tid + i * TPB) * 16);
                }
                asm volatile("cp.async.commit_group;");
            } else {
                __syncthreads();
            }

            // ---- pass 2: exact fp32 verification of candidates within T ----
            const float T0 = bestd[rloc] + EPRUNE;
            const float T1 = bestd[rloc + 8] + EPRUNE;
            const float* r0p = resF + (half * 64 + rloc) * RPAD;
            const float* r1p = resF + (half * 64 + rloc + 8) * RPAD;
            float e0d = 3.402823466e38f, e1d = 3.402823466e38f;
            int   e0i = KCB,             e1i = KCB;
            #pragma unroll 1
            for (int nt = 0; nt < 16; nt++) {
                int c = cbase + nt * 8;
                float cn0 = cnl[c], cn1 = cnl[c + 1];
                float d;
                d = fmaf(-2.f, acc[nt][0], cn0);
                if (d <= T0) {
                    float de = exact_dist(r0p, cb + ((size_t)(l * KCB + c) << 7), cn0);
                    if (de < e0d || (de == e0d && c < e0i)) { e0d = de; e0i = c; }
                }
                d = fmaf(-2.f, acc[nt][1], cn1);
                if (d <= T0) {
                    float de = exact_dist(r0p, cb + ((size_t)(l * KCB + c + 1) << 7), cn1);
                    if (de < e0d || (de == e0d && c + 1 < e0i)) { e0d = de; e0i = c + 1; }
                }
                d = fmaf(-2.f, acc[nt][2], cn0);
                if (d <= T1) {
                    float de = exact_dist(r1p, cb + ((size_t)(l * KCB + c) << 7), cn0);
                    if (de < e1d || (de == e1d && c < e1i)) { e1d = de; e1i = c; }
                }
                d = fmaf(-2.f, acc[nt][3], cn1);
                if (d <= T1) {
                    float de = exact_dist(r1p, cb + ((size_t)(l * KCB + c + 1) << 7), cn1);
                    if (de < e1d || (de == e1d && c + 1 < e1i)) { e1d = de; e1i = c + 1; }
                }
            }
            #pragma unroll
            for (int off = 1; off <= 2; off <<= 1) {
                float od = __shfl_xor_sync(0xffffffffu, e0d, off);
                int   oi = __shfl_xor_sync(0xffffffffu, e0i, off);
                if (od < e0d || (od == e0d && oi < e0i)) { e0d = od; e0i = oi; }
                od = __shfl_xor_sync(0xffffffffu, e1d, off);
                oi = __shfl_xor_sync(0xffffffffu, e1i, off);
                if (od < e1d || (od == e1d && oi < e1i)) { e1d = od; e1i = oi; }
            }
            if (warp_n == 0 && (lane & 3) == 0) {
                exd[rloc] = e0d;     exi[rloc] = e0i;
                exd[rloc + 8] = e1d; exi[rloc + 8] = e1i;
            }
            __syncthreads();
            if (warp_n == 1 && (lane & 3) == 0) {
                if (e0d < exd[rloc] || (e0d == exd[rloc] && e0i < exi[rloc])) {
                    exd[rloc] = e0d; exi[rloc] = e0i;
                }
                if (e1d < exd[rloc + 8] || (e1d == exd[rloc + 8] && e1i < exi[rloc + 8])) {
                    exd[rloc + 8] = e1d; exi[rloc + 8] = e1i;
                }
            }
            __syncthreads();

            // ---- residual update + codes for this half ----
            #pragma unroll
            for (int i = 0; i < 8; i++) {
                int idx = tid + i * TPB;             // 64*32 float4
                int row = idx >> 5, c4 = idx & 31;
                int win = exi[row];
                float4 c = __ldg((const float4*)(cb + ((size_t)(l * KCB + win) << 7)) + c4);
                float4* rp = (float4*)(resF + (half * 64 + row) * RPAD) + c4;
                float4 rv = *rp;
                *rp = make_float4(rv.x - c.x, rv.y - c.y, rv.z - c.z, rv.w - c.w);
            }
            if (write_codes && tid < 64)
                out_codes[(row0 + half * 64 + tid) * NLEV + l] = (float)exi[tid];
            __syncthreads();
        }
    }

    // ---- recon = x - residual_final ----
    float4* o4 = (float4*)(out_recon + row0 * DIM);
    #pragma unroll
    for (int i = 0; i < 16; i++) {
        int idx = tid + i * TPB;
        int row = idx >> 5, c4 = idx & 31;
        float4 xv = x4[idx];
        float4 rv = ((float4*)(resF + row * RPAD))[c4];
        o4[idx] = make_float4(xv.x - rv.x, xv.y - rv.y, xv.z - rv.z, xv.w - rv.w);
    }
}

// ---------------------------------------------------------------------------
extern "C" void kernel_launch(void* const* d_in, const int* in_sizes, int n_in,
                              void* d_out, int out_size) {
    const float* x  = (const float*)d_in[0];
    const float* cb = (const float*)d_in[1];
    int nx = in_sizes[0];
    int nc = (n_in > 1) ? in_sizes[1] : 0;
    if (nx == NLEV * KCB * DIM && nc != NLEV * KCB * DIM) {
        const float* t = x; x = cb; cb = t;
        int ts = nx; nx = nc; nc = ts;
    }
    const int B = nx / DIM;

    float* out       = (float*)d_out;
    float* out_codes = out + (size_t)B * DIM;
    int write_codes  = (out_size >= B * DIM + B * NLEV) ? 1 : 0;

    rq_prep_kernel<<<(NLEV * KCB * DIM + 255) / 256, 256>>>(cb);

    cudaFuncSetAttribute(rq_main_kernel,
                         cudaFuncAttributeMaxDynamicSharedMemorySize, SM_TOTAL);
    rq_main_kernel<<<B / ROWS, TPB, SM_TOTAL>>>(x, cb, out, out_codes, write_codes);
}

// round 16
// speedup vs baseline: 1.1499x; 1.1499x over previous
#include <cuda_runtime.h>
#include <cuda_bf16.h>
#include <cstdint>

#define NLEV 4
#define KCB  256
#define DIM  128
#define ROWS 128
#define TPB  512
#define PAD  136                 // bf16 halves per padded tile row (conflict-free ldmatrix)
#define RPAD 132                 // floats per padded residual row (conflict-free verify)
#define EPRUNE 0.5f

// ---------------- global scratch (allocation-free rule) ----------------
__device__ unsigned short g_cbH[NLEV * KCB * PAD];   // bf16(hi) codebook, padded rows
__device__ float g_cnorm[NLEV * KCB];

// ---------------- prep: bf16 codebook + norms ----------------
__global__ void rq_prep_kernel(const float* __restrict__ cb) {
    int i = blockIdx.x * blockDim.x + threadIdx.x;
    const int total = NLEV * KCB * DIM;
    if (i < total) {
        int l = i / (KCB * DIM);
        int rem = i - l * (KCB * DIM);
        int e = rem >> 7, k = rem & 127;
        g_cbH[(l * KCB + e) * PAD + k] =
            __bfloat16_as_ushort(__float2bfloat16(cb[i]));
    }
    if (i < NLEV * KCB) {
        const float* p = cb + (size_t)i * DIM;
        float s = 0.0f;
        #pragma unroll 1
        for (int k = 0; k < DIM; k++) s = fmaf(p[k], p[k], s);
        g_cnorm[i] = s;
    }
}

// ---------------- PTX helpers (baseline sm_80+ features only) ----------------
__device__ __forceinline__ uint32_t smem_u32(const void* p) {
    uint32_t a;
    asm("{ .reg .u64 t; cvta.to.shared.u64 t, %1; cvt.u32.u64 %0, t; }" : "=r"(a) : "l"(p));
    return a;
}
__device__ __forceinline__ void cp16(uint32_t s, const void* g) {
    asm volatile("cp.async.cg.shared.global [%0], [%1], 16;" :: "r"(s), "l"(g));
}
__device__ __forceinline__ void ldsm_x4(uint32_t& r0, uint32_t& r1, uint32_t& r2, uint32_t& r3,
                                        uint32_t addr) {
    asm volatile("ldmatrix.sync.aligned.m8n8.x4.shared.b16 {%0,%1,%2,%3}, [%4];"
                 : "=r"(r0), "=r"(r1), "=r"(r2), "=r"(r3) : "r"(addr));
}
__device__ __forceinline__ void mma16816(float* d,
                                         uint32_t a0, uint32_t a1, uint32_t a2, uint32_t a3,
                                         uint32_t b0, uint32_t b1) {
    asm volatile("mma.sync.aligned.m16n8k16.row.col.f32.bf16.bf16.f32 "
                 "{%0,%1,%2,%3}, {%4,%5,%6,%7}, {%8,%9}, {%0,%1,%2,%3};"
                 : "+f"(d[0]), "+f"(d[1]), "+f"(d[2]), "+f"(d[3])
                 : "r"(a0), "r"(a1), "r"(a2), "r"(a3), "r"(b0), "r"(b1));
}

// exact fp32 distance (sequential-k fmaf — same arithmetic as R4-R12)
__device__ __forceinline__ float exact_dist(const float* resRow, const float* cbRow, float cn) {
    float s = 0.0f;
    #pragma unroll
    for (int k4 = 0; k4 < 32; k4++) {
        float4 c = __ldg((const float4*)cbRow + k4);
        float4 r = ((const float4*)resRow)[k4];
        s = fmaf(r.x, c.x, s); s = fmaf(r.y, c.y, s);
        s = fmaf(r.z, c.z, s); s = fmaf(r.w, c.w, s);
    }
    return fmaf(-2.0f, s, cn);
}

// ---------------- smem layout (bytes) ----------------
#define SM_B     0                      // 256*136*2 = 69632
#define SM_AHI   69632                  // 128*136*2 = 34816
#define SM_ALO   104448                 // 34816
#define SM_RES   139264                 // 128*132*4 = 67584
#define SM_CN    206848                 // 4096
#define SM_BESTD 210944                 // 128*4
#define SM_EXD   211456                 // 128*4
#define SM_EXI   211968                 // 128*4
#define SM_TOTAL 212480

#define NB16CHUNKS (KCB * PAD * 2 / 16)   // 4352 16B chunks per B level

extern __shared__ __align__(16) char smem[];

__global__ void __launch_bounds__(TPB)
rq_main_kernel(const float* __restrict__ x,
               const float* __restrict__ cb,
               float* __restrict__ out_recon,
               float* __restrict__ out_codes,
               int write_codes) {
    const int tid    = threadIdx.x;
    const int lane   = tid & 31;
    const int wid    = tid >> 5;
    const int warp_m = wid & 7;          // 16-row group within 128 rows
    const int warp_n = wid >> 3;         // 128-entry half
    const long long row0 = (long long)blockIdx.x * ROWS;
    const uint32_t sbase = smem_u32(smem);

    float* resF  = (float*)(smem + SM_RES);
    float* shCn  = (float*)(smem + SM_CN);
    float* bestd = (float*)(smem + SM_BESTD);
    float* exd   = (float*)(smem + SM_EXD);
    int*   exi   = (int*)  (smem + SM_EXI);

    // cnorms -> smem (1024 floats)
    if (tid < 256) ((float4*)shCn)[tid] = ((const float4*)g_cnorm)[tid];

    // x tile -> padded fp32 residual
    const float4* x4 = (const float4*)(x + row0 * DIM);
    #pragma unroll
    for (int i = 0; i < 8; i++) {
        int idx = tid + i * TPB;         // 128*32 float4
        int row = idx >> 5, c4 = idx & 31;
        ((float4*)(resF + row * RPAD))[c4] = x4[idx];
    }

    // stage level-0 B
    {
        const char* gsrc = (const char*)g_cbH;
        #pragma unroll
        for (int i = 0; i < 9; i++) {
            int idx = tid + i * TPB;
            if (idx < NB16CHUNKS)
                cp16(sbase + SM_B + idx * 16, gsrc + (size_t)idx * 16);
        }
        asm volatile("cp.async.commit_group;");
    }

    // R13 bug: level-0 convert read resF rows written by OTHER threads with no
    // barrier in between. Make the residual tile visible block-wide first.
    __syncthreads();

    // ldmatrix address components (constant across levels)
    const int arow = warp_m * 16 + (lane & 15);
    const uint32_t aoff = (uint32_t)(arow * PAD + ((lane >> 4) << 3)) * 2;
    const int bErow = warp_n * 128 + ((lane >> 4) << 3) + (lane & 7);
    const uint32_t bko  = (uint32_t)(((lane >> 3) & 1) << 3);
    const int rloc = warp_m * 16 + (lane >> 2);      // epilogue row (plus +8)

    for (int l = 0; l < NLEV; l++) {
        // ---- convert residual rows to bf16 hi/lo A tiles (R12-proven scalar path) ----
        #pragma unroll 4
        for (int i = 0; i < 16; i++) {
            int idx = tid + i * TPB;                 // 128*64 float2 pairs
            int row = idx >> 6;
            int kp  = (idx & 63) * 2;
            float2 v = *(const float2*)(resF + row * RPAD + kp);
            __nv_bfloat16 h0 = __float2bfloat16(v.x);
            __nv_bfloat16 h1 = __float2bfloat16(v.y);
            __nv_bfloat16 l0 = __float2bfloat16(v.x - __bfloat162float(h0));
            __nv_bfloat16 l1 = __float2bfloat16(v.y - __bfloat162float(h1));
            *(uint32_t*)(smem + SM_AHI + (row * PAD + kp) * 2) =
                ((uint32_t)__bfloat16_as_ushort(h1) << 16) | __bfloat16_as_ushort(h0);
            *(uint32_t*)(smem + SM_ALO + (row * PAD + kp) * 2) =
                ((uint32_t)__bfloat16_as_ushort(l1) << 16) | __bfloat16_as_ushort(l0);
        }
        // B staged?  (group committed by prologue / previous level's prefetch)
        asm volatile("cp.async.wait_group 0;" ::: "memory");
        __syncthreads();
        const float* cnl = shCn + l * KCB;

        // ---- GEMM: acc = dot(r_hi+r_lo, c_hi) for 16 rows x 128 entries/warp ----
        float acc[16][4];
        #pragma unroll
        for (int nt = 0; nt < 16; nt++) {
            acc[nt][0] = 0.f; acc[nt][1] = 0.f; acc[nt][2] = 0.f; acc[nt][3] = 0.f;
        }
        {
            const uint32_t Ah = sbase + SM_AHI + aoff;
            const uint32_t Al = sbase + SM_ALO + aoff;
            const uint32_t Bb = sbase + SM_B + (uint32_t)(bErow * PAD + bko) * 2;
            #pragma unroll
            for (int ks = 0; ks < 8; ks++) {
                uint32_t h0, h1, h2, h3, l0, l1, l2, l3;
                ldsm_x4(h0, h1, h2, h3, Ah + ks * 32);
                ldsm_x4(l0, l1, l2, l3, Al + ks * 32);
                #pragma unroll
                for (int nt = 0; nt < 16; nt += 2) {
                    uint32_t b0, b1, b2, b3;
                    ldsm_x4(b0, b1, b2, b3, Bb + (uint32_t)(nt * 8 * PAD + ks * 16) * 2);
                    mma16816(acc[nt],     h0, h1, h2, h3, b0, b1);
                    mma16816(acc[nt],     l0, l1, l2, l3, b0, b1);
                    mma16816(acc[nt + 1], h0, h1, h2, h3, b2, b3);
                    mma16816(acc[nt + 1], l0, l1, l2, l3, b2, b3);
                }
            }
        }

        // ---- pass 1: approx per-row min (value only -> threshold) ----
        const int cbase = warp_n * 128 + (lane & 3) * 2;
        float m0 = 3.402823466e38f, m1 = 3.402823466e38f;
        #pragma unroll
        for (int nt = 0; nt < 16; nt++) {
            int c = cbase + nt * 8;
            float cn0 = cnl[c], cn1 = cnl[c + 1];
            m0 = fminf(m0, fmaf(-2.f, acc[nt][0], cn0));
            m0 = fminf(m0, fmaf(-2.f, acc[nt][1], cn1));
            m1 = fminf(m1, fmaf(-2.f, acc[nt][2], cn0));
            m1 = fminf(m1, fmaf(-2.f, acc[nt][3], cn1));
        }
        m0 = fminf(m0, __shfl_xor_sync(0xffffffffu, m0, 1));
        m0 = fminf(m0, __shfl_xor_sync(0xffffffffu, m0, 2));
        m1 = fminf(m1, __shfl_xor_sync(0xffffffffu, m1, 1));
        m1 = fminf(m1, __shfl_xor_sync(0xffffffffu, m1, 2));
        if (warp_n == 0 && (lane & 3) == 0) { bestd[rloc] = m0; bestd[rloc + 8] = m1; }
        __syncthreads();
        if (warp_n == 1 && (lane & 3) == 0) {
            if (m0 < bestd[rloc])     bestd[rloc]     = m0;
            if (m1 < bestd[rloc + 8]) bestd[rloc + 8] = m1;
        }
        __syncthreads();

        // overlap: prefetch next level's B now (B smem is dead after the GEMM)
        if (l + 1 < NLEV) {
            const char* gsrc = (const char*)g_cbH + (size_t)(l + 1) * KCB * PAD * 2;
            #pragma unroll
            for (int i = 0; i < 9; i++) {
                int idx = tid + i * TPB;
                if (idx < NB16CHUNKS)
                    cp16(sbase + SM_B + idx * 16, gsrc + (size_t)idx * 16);
            }
            asm volatile("cp.async.commit_group;");
        }

        // ---- pass 2: exact fp32 verification of candidates within T ----
        const float T0 = bestd[rloc] + EPRUNE;
        const float T1 = bestd[rloc + 8] + EPRUNE;
        const float* r0p = resF + rloc * RPAD;
        const float* r1p = resF + (rloc + 8) * RPAD;
        float e0d = 3.402823466e38f, e1d = 3.402823466e38f;
        int   e0i = KCB,             e1i = KCB;
        #pragma unroll 1
        for (int nt = 0; nt < 16; nt++) {
            int c = cbase + nt * 8;
            float cn0 = cnl[c], cn1 = cnl[c + 1];
            float d;
            d = fmaf(-2.f, acc[nt][0], cn0);
            if (d <= T0) {
                float de = exact_dist(r0p, cb + ((size_t)(l * KCB + c) << 7), cn0);
                if (de < e0d || (de == e0d && c < e0i)) { e0d = de; e0i = c; }
            }
            d = fmaf(-2.f, acc[nt][1], cn1);
            if (d <= T0) {
                float de = exact_dist(r0p, cb + ((size_t)(l * KCB + c + 1) << 7), cn1);
                if (de < e0d || (de == e0d && c + 1 < e0i)) { e0d = de; e0i = c + 1; }
            }
            d = fmaf(-2.f, acc[nt][2], cn0);
            if (d <= T1) {
                float de = exact_dist(r1p, cb + ((size_t)(l * KCB + c) << 7), cn0);
                if (de < e1d || (de == e1d && c < e1i)) { e1d = de; e1i = c; }
            }
            d = fmaf(-2.f, acc[nt][3], cn1);
            if (d <= T1) {
                float de = exact_dist(r1p, cb + ((size_t)(l * KCB + c + 1) << 7), cn1);
                if (de < e1d || (de == e1d && c + 1 < e1i)) { e1d = de; e1i = c + 1; }
            }
        }
        #pragma unroll
        for (int off = 1; off <= 2; off <<= 1) {
            float od = __shfl_xor_sync(0xffffffffu, e0d, off);
            int   oi = __shfl_xor_sync(0xffffffffu, e0i, off);
            if (od < e0d || (od == e0d && oi < e0i)) { e0d = od; e0i = oi; }
            od = __shfl_xor_sync(0xffffffffu, e1d, off);
            oi = __shfl_xor_sync(0xffffffffu, e1i, off);
            if (od < e1d || (od == e1d && oi < e1i)) { e1d = od; e1i = oi; }
        }
        if (warp_n == 0 && (lane & 3) == 0) {
            exd[rloc] = e0d;     exi[rloc] = e0i;
            exd[rloc + 8] = e1d; exi[rloc + 8] = e1i;
        }
        __syncthreads();
        if (warp_n == 1 && (lane & 3) == 0) {
            if (e0d < exd[rloc] || (e0d == exd[rloc] && e0i < exi[rloc])) {
                exd[rloc] = e0d; exi[rloc] = e0i;
            }
            if (e1d < exd[rloc + 8] || (e1d == exd[rloc + 8] && e1i < exi[rloc + 8])) {
                exd[rloc + 8] = e1d; exi[rloc + 8] = e1i;
            }
        }
        __syncthreads();

        // ---- residual update + codes ----
        #pragma unroll
        for (int i = 0; i < 8; i++) {
            int idx = tid + i * TPB;                 // 128*32 float4
            int row = idx >> 5, c4 = idx & 31;
            int win = exi[row];
            float4 c = __ldg((const float4*)(cb + ((size_t)(l * KCB + win) << 7)) + c4);
            float4* rp = (float4*)(resF + row * RPAD) + c4;
            float4 rv = *rp;
            *rp = make_float4(rv.x - c.x, rv.y - c.y, rv.z - c.z, rv.w - c.w);
        }
        if (write_codes && tid < ROWS)
            out_codes[(row0 + tid) * NLEV + l] = (float)exi[tid];
        __syncthreads();
    }

    // ---- recon = x - residual_final ----
    float4* o4 = (float4*)(out_recon + row0 * DIM);
    #pragma unroll
    for (int i = 0; i < 8; i++) {
        int idx = tid + i * TPB;
        int row = idx >> 5, c4 = idx & 31;
        float4 xv = x4[idx];
        float4 rv = ((float4*)(resF + row * RPAD))[c4];
        o4[idx] = make_float4(xv.x - rv.x, xv.y - rv.y, xv.z - rv.z, xv.w - rv.w);
    }
}

// ---------------------------------------------------------------------------
extern "C" void kernel_launch(void* const* d_in, const int* in_sizes, int n_in,
                              void* d_out, int out_size) {
    const float* x  = (const float*)d_in[0];
    const float* cb = (const float*)d_in[1];
    int nx = in_sizes[0];
    int nc = (n_in > 1) ? in_sizes[1] : 0;
    if (nx == NLEV * KCB * DIM && nc != NLEV * KCB * DIM) {
        const float* t = x; x = cb; cb = t;
        int ts = nx; nx = nc; nc = ts;
    }
    const int B = nx / DIM;

    float* out       = (float*)d_out;
    float* out_codes = out + (size_t)B * DIM;
    int write_codes  = (out_size >= B * DIM + B * NLEV) ? 1 : 0;

    rq_prep_kernel<<<(NLEV * KCB * DIM + 255) / 256, 256>>>(cb);

    cudaFuncSetAttribute(rq_main_kernel,
                         cudaFuncAttributeMaxDynamicSharedMemorySize, SM_TOTAL);
    rq_main_kernel<<<B / ROWS, TPB, SM_TOTAL>>>(x, cb, out, out_codes, write_codes);
}

// round 17
// speedup vs baseline: 1.3738x; 1.1947x over previous
#include <cuda_runtime.h>
#include <cuda_bf16.h>
#include <cstdint>

#define NLEV 4
#define KCB  256
#define DIM  128
#define ROWS 128
#define TPB  512
#define PAD  136                 // bf16 halves per padded tile row (conflict-free ldmatrix)
#define RPAD 132                 // floats per padded residual row (conflict-free verify)
#define EPRUNE 0.5f
#define LCAP 128                 // per-warp candidate list capacity

// ---------------- global scratch (allocation-free rule) ----------------
__device__ unsigned short g_cbH[NLEV * KCB * PAD];   // bf16(hi) codebook, padded rows
__device__ float g_cnorm[NLEV * KCB];

// ---------------- prep: bf16 codebook + norms ----------------
__global__ void rq_prep_kernel(const float* __restrict__ cb) {
    int i = blockIdx.x * blockDim.x + threadIdx.x;
    const int total = NLEV * KCB * DIM;
    if (i < total) {
        int l = i / (KCB * DIM);
        int rem = i - l * (KCB * DIM);
        int e = rem >> 7, k = rem & 127;
        g_cbH[(l * KCB + e) * PAD + k] =
            __bfloat16_as_ushort(__float2bfloat16(cb[i]));
    }
    if (i < NLEV * KCB) {
        const float* p = cb + (size_t)i * DIM;
        float s = 0.0f;
        #pragma unroll 1
        for (int k = 0; k < DIM; k++) s = fmaf(p[k], p[k], s);
        g_cnorm[i] = s;
    }
}

// ---------------- PTX helpers (baseline sm_80+ features only) ----------------
__device__ __forceinline__ uint32_t smem_u32(const void* p) {
    uint32_t a;
    asm("{ .reg .u64 t; cvta.to.shared.u64 t, %1; cvt.u32.u64 %0, t; }" : "=r"(a) : "l"(p));
    return a;
}
__device__ __forceinline__ void cp16(uint32_t s, const void* g) {
    asm volatile("cp.async.cg.shared.global [%0], [%1], 16;" :: "r"(s), "l"(g));
}
__device__ __forceinline__ void ldsm_x4(uint32_t& r0, uint32_t& r1, uint32_t& r2, uint32_t& r3,
                                        uint32_t addr) {
    asm volatile("ldmatrix.sync.aligned.m8n8.x4.shared.b16 {%0,%1,%2,%3}, [%4];"
                 : "=r"(r0), "=r"(r1), "=r"(r2), "=r"(r3) : "r"(addr));
}
__device__ __forceinline__ void mma16816(float* d,
                                         uint32_t a0, uint32_t a1, uint32_t a2, uint32_t a3,
                                         uint32_t b0, uint32_t b1) {
    asm volatile("mma.sync.aligned.m16n8k16.row.col.f32.bf16.bf16.f32 "
                 "{%0,%1,%2,%3}, {%4,%5,%6,%7}, {%8,%9}, {%0,%1,%2,%3};"
                 : "+f"(d[0]), "+f"(d[1]), "+f"(d[2]), "+f"(d[3])
                 : "r"(a0), "r"(a1), "r"(a2), "r"(a3), "r"(b0), "r"(b1));
}

// monotonic float<->uint (order-preserving, works for negatives)
__device__ __forceinline__ uint32_t f2mono(float f) {
    uint32_t u = __float_as_uint(f);
    return (u & 0x80000000u) ? ~u : (u | 0x80000000u);
}
__device__ __forceinline__ float mono2f(uint32_t m) {
    uint32_t u = (m & 0x80000000u) ? (m & 0x7fffffffu) : ~m;
    return __uint_as_float(u);
}

// exact fp32 distance, full-row serial (R16-proven; fallback path only)
__device__ __forceinline__ float exact_dist(const float* resRow, const float* cbRow, float cn) {
    float s = 0.0f;
    #pragma unroll
    for (int k4 = 0; k4 < 32; k4++) {
        float4 c = __ldg((const float4*)cbRow + k4);
        float4 r = ((const float4*)resRow)[k4];
        s = fmaf(r.x, c.x, s); s = fmaf(r.y, c.y, s);
        s = fmaf(r.z, c.z, s); s = fmaf(r.w, c.w, s);
    }
    return fmaf(-2.0f, s, cn);
}

// ---------------- smem layout (bytes) ----------------
#define SM_B     0                      // 256*136*2 = 69632
#define SM_AHI   69632                  // 34816
#define SM_ALO   104448                 // 34816
#define SM_RES   139264                 // 128*132*4 = 67584
#define SM_CN    206848                 // 4096
#define SM_BESTU 210944                 // 128*4 = 512
#define SM_EXP   211456                 // 128*8 = 1024 (u64 packed dist|idx)
#define SM_LIST  212480                 // 16 warps * 128 * 4 = 8192
#define SM_TOTAL 220672

#define NB16CHUNKS (KCB * PAD * 2 / 16)   // 4352 16B chunks per B level

extern __shared__ __align__(16) char smem[];

__global__ void __launch_bounds__(TPB)
rq_main_kernel(const float* __restrict__ x,
               const float* __restrict__ cb,
               float* __restrict__ out_recon,
               float* __restrict__ out_codes,
               int write_codes) {
    const int tid    = threadIdx.x;
    const int lane   = tid & 31;
    const int wid    = tid >> 5;
    const int warp_m = wid & 7;          // 16-row group within 128 rows
    const int warp_n = wid >> 3;         // 128-entry half
    const long long row0 = (long long)blockIdx.x * ROWS;
    const uint32_t sbase = smem_u32(smem);

    float* resF  = (float*)(smem + SM_RES);
    float* shCn  = (float*)(smem + SM_CN);
    uint32_t* bestU = (uint32_t*)(smem + SM_BESTU);
    unsigned long long* exP = (unsigned long long*)(smem + SM_EXP);
    uint32_t* wlist = (uint32_t*)(smem + SM_LIST) + wid * LCAP;

    // cnorms -> smem (1024 floats)
    if (tid < 256) ((float4*)shCn)[tid] = ((const float4*)g_cnorm)[tid];

    // x tile -> padded fp32 residual
    const float4* x4 = (const float4*)(x + row0 * DIM);
    #pragma unroll
    for (int i = 0; i < 8; i++) {
        int idx = tid + i * TPB;         // 128*32 float4
        int row = idx >> 5, c4 = idx & 31;
        ((float4*)(resF + row * RPAD))[c4] = x4[idx];
    }

    // stage level-0 B
    {
        const char* gsrc = (const char*)g_cbH;
        #pragma unroll
        for (int i = 0; i < 9; i++) {
            int idx = tid + i * TPB;
            if (idx < NB16CHUNKS)
                cp16(sbase + SM_B + idx * 16, gsrc + (size_t)idx * 16);
        }
        asm volatile("cp.async.commit_group;");
    }

    // residual tile must be block-visible before level-0 convert (R13 lesson)
    __syncthreads();

    // ldmatrix address components (constant across levels)
    const int arow = warp_m * 16 + (lane & 15);
    const uint32_t aoff = (uint32_t)(arow * PAD + ((lane >> 4) << 3)) * 2;
    const int bErow = warp_n * 128 + ((lane >> 4) << 3) + (lane & 7);
    const uint32_t bko  = (uint32_t)(((lane >> 3) & 1) << 3);
    const int rloc = warp_m * 16 + (lane >> 2);      // this lane's row (plus +8)

    for (int l = 0; l < NLEV; l++) {
        // per-level reduction-state init (visible after the sync below)
        if (tid < ROWS) { bestU[tid] = 0xffffffffu; exP[tid] = ~0ull; }

        // ---- convert residual rows to bf16 hi/lo A tiles ----
        #pragma unroll 4
        for (int i = 0; i < 16; i++) {
            int idx = tid + i * TPB;                 // 128*64 float2 pairs
            int row = idx >> 6;
            int kp  = (idx & 63) * 2;
            float2 v = *(const float2*)(resF + row * RPAD + kp);
            __nv_bfloat16 h0 = __float2bfloat16(v.x);
            __nv_bfloat16 h1 = __float2bfloat16(v.y);
            __nv_bfloat16 l0 = __float2bfloat16(v.x - __bfloat162float(h0));
            __nv_bfloat16 l1 = __float2bfloat16(v.y - __bfloat162float(h1));
            *(uint32_t*)(smem + SM_AHI + (row * PAD + kp) * 2) =
                ((uint32_t)__bfloat16_as_ushort(h1) << 16) | __bfloat16_as_ushort(h0);
            *(uint32_t*)(smem + SM_ALO + (row * PAD + kp) * 2) =
                ((uint32_t)__bfloat16_as_ushort(l1) << 16) | __bfloat16_as_ushort(l0);
        }
        asm volatile("cp.async.wait_group 0;" ::: "memory");
        __syncthreads();
        const float* cnl = shCn + l * KCB;

        // ---- GEMM: acc = dot(r_hi+r_lo, c_hi) for 16 rows x 128 entries/warp ----
        float acc[16][4];
        #pragma unroll
        for (int nt = 0; nt < 16; nt++) {
            acc[nt][0] = 0.f; acc[nt][1] = 0.f; acc[nt][2] = 0.f; acc[nt][3] = 0.f;
        }
        {
            const uint32_t Ah = sbase + SM_AHI + aoff;
            const uint32_t Al = sbase + SM_ALO + aoff;
            const uint32_t Bb = sbase + SM_B + (uint32_t)(bErow * PAD + bko) * 2;
            #pragma unroll
            for (int ks = 0; ks < 8; ks++) {
                uint32_t h0, h1, h2, h3, l0, l1, l2, l3;
                ldsm_x4(h0, h1, h2, h3, Ah + ks * 32);
                ldsm_x4(l0, l1, l2, l3, Al + ks * 32);
                #pragma unroll
                for (int nt = 0; nt < 16; nt += 2) {
                    uint32_t b0, b1, b2, b3;
                    ldsm_x4(b0, b1, b2, b3, Bb + (uint32_t)(nt * 8 * PAD + ks * 16) * 2);
                    mma16816(acc[nt],     h0, h1, h2, h3, b0, b1);
                    mma16816(acc[nt],     l0, l1, l2, l3, b0, b1);
                    mma16816(acc[nt + 1], h0, h1, h2, h3, b2, b3);
                    mma16816(acc[nt + 1], l0, l1, l2, l3, b2, b3);
                }
            }
        }

        // ---- pass 1: approx per-row min via monotonic-uint atomicMin ----
        const int cbase = warp_n * 128 + (lane & 3) * 2;
        float m0 = 3.402823466e38f, m1 = 3.402823466e38f;
        #pragma unroll
        for (int nt = 0; nt < 16; nt++) {
            int c = cbase + nt * 8;
            float cn0 = cnl[c], cn1 = cnl[c + 1];
            m0 = fminf(m0, fmaf(-2.f, acc[nt][0], cn0));
            m0 = fminf(m0, fmaf(-2.f, acc[nt][1], cn1));
            m1 = fminf(m1, fmaf(-2.f, acc[nt][2], cn0));
            m1 = fminf(m1, fmaf(-2.f, acc[nt][3], cn1));
        }
        m0 = fminf(m0, __shfl_xor_sync(0xffffffffu, m0, 1));
        m0 = fminf(m0, __shfl_xor_sync(0xffffffffu, m0, 2));
        m1 = fminf(m1, __shfl_xor_sync(0xffffffffu, m1, 1));
        m1 = fminf(m1, __shfl_xor_sync(0xffffffffu, m1, 2));
        if ((lane & 3) == 0) {
            atomicMin(&bestU[rloc],     f2mono(m0));
            atomicMin(&bestU[rloc + 8], f2mono(m1));
        }
        __syncthreads();

        // overlap: prefetch next level's B now (B smem is dead after the GEMM)
        if (l + 1 < NLEV) {
            const char* gsrc = (const char*)g_cbH + (size_t)(l + 1) * KCB * PAD * 2;
            #pragma unroll
            for (int i = 0; i < 9; i++) {
                int idx = tid + i * TPB;
                if (idx < NB16CHUNKS)
                    cp16(sbase + SM_B + idx * 16, gsrc + (size_t)idx * 16);
            }
            asm volatile("cp.async.commit_group;");
        }

        // ---- pass 2a: ballot-compact candidates (d <= T) into per-warp list ----
        const float T0 = mono2f(bestU[rloc]) + EPRUNE;
        const float T1 = mono2f(bestU[rloc + 8]) + EPRUNE;
        const int rL0 = lane >> 2;              // warp-local rows
        const int rL1 = (lane >> 2) + 8;
        unsigned cnt = 0;                       // warp-uniform
        #pragma unroll 1
        for (int nt = 0; nt < 16; nt++) {
            int c = cbase + nt * 8;
            float cn0 = cnl[c], cn1 = cnl[c + 1];
            float d0 = fmaf(-2.f, acc[nt][0], cn0);
            float d1 = fmaf(-2.f, acc[nt][1], cn1);
            float d2 = fmaf(-2.f, acc[nt][2], cn0);
            float d3 = fmaf(-2.f, acc[nt][3], cn1);
            uint32_t mk, below = (1u << lane) - 1u;
            mk = __ballot_sync(0xffffffffu, d0 <= T0);
            if (d0 <= T0 && cnt + __popc(mk & below) < LCAP)
                wlist[cnt + __popc(mk & below)] = ((uint32_t)rL0 << 8) | (uint32_t)c;
            cnt += __popc(mk);
            mk = __ballot_sync(0xffffffffu, d1 <= T0);
            if (d1 <= T0 && cnt + __popc(mk & below) < LCAP)
                wlist[cnt + __popc(mk & below)] = ((uint32_t)rL0 << 8) | (uint32_t)(c + 1);
            cnt += __popc(mk);
            mk = __ballot_sync(0xffffffffu, d2 <= T1);
            if (d2 <= T1 && cnt + __popc(mk & below) < LCAP)
                wlist[cnt + __popc(mk & below)] = ((uint32_t)rL1 << 8) | (uint32_t)c;
            cnt += __popc(mk);
            mk = __ballot_sync(0xffffffffu, d3 <= T1);
            if (d3 <= T1 && cnt + __popc(mk & below) < LCAP)
                wlist[cnt + __popc(mk & below)] = ((uint32_t)rL1 << 8) | (uint32_t)(c + 1);
            cnt += __popc(mk);
        }

        // ---- pass 2b: verify candidates; quad-parallel exact fp32 distance ----
        if (cnt <= LCAP) {
            const int q = lane & 3;
            #pragma unroll 1
            for (unsigned base = 0; base < cnt; base += 8) {
                unsigned ci = base + (lane >> 2);
                bool valid = (ci < cnt);
                uint32_t item = valid ? wlist[ci] : 0u;
                int rowL  = (item >> 8) & 15;
                int entry = item & 255;
                int rowG  = warp_m * 16 + rowL;
                // lane q sums k in [q*32, q*32+32) sequentially (fp32 fmaf)
                const float4* cc = (const float4*)(cb + ((size_t)(l * KCB + entry) << 7)) + q * 8;
                const float4* rr = (const float4*)(resF + rowG * RPAD) + q * 8;
                float s = 0.0f;
                #pragma unroll
                for (int k4 = 0; k4 < 8; k4++) {
                    float4 c = __ldg(cc + k4);
                    float4 r = rr[k4];
                    s = fmaf(r.x, c.x, s); s = fmaf(r.y, c.y, s);
                    s = fmaf(r.z, c.z, s); s = fmaf(r.w, c.w, s);
                }
                s += __shfl_xor_sync(0xffffffffu, s, 1);
                s += __shfl_xor_sync(0xffffffffu, s, 2);
                if (valid && q == 0) {
                    float dex = fmaf(-2.0f, s, cnl[entry]);
                    unsigned long long pk =
                        ((unsigned long long)f2mono(dex) << 32) | (unsigned)entry;
                    atomicMin(&exP[rowG], pk);
                }
            }
        } else {
            // overflow fallback: R16-proven serial verification (rare/never)
            const float* r0p = resF + rloc * RPAD;
            const float* r1p = resF + (rloc + 8) * RPAD;
            #pragma unroll 1
            for (int nt = 0; nt < 16; nt++) {
                int c = cbase + nt * 8;
                float cn0 = cnl[c], cn1 = cnl[c + 1];
                float d;
                d = fmaf(-2.f, acc[nt][0], cn0);
                if (d <= T0) {
                    float de = exact_dist(r0p, cb + ((size_t)(l * KCB + c) << 7), cn0);
                    atomicMin(&exP[rloc], ((unsigned long long)f2mono(de) << 32) | (unsigned)c);
                }
                d = fmaf(-2.f, acc[nt][1], cn1);
                if (d <= T0) {
                    float de = exact_dist(r0p, cb + ((size_t)(l * KCB + c + 1) << 7), cn1);
                    atomicMin(&exP[rloc], ((unsigned long long)f2mono(de) << 32) | (unsigned)(c + 1));
                }
                d = fmaf(-2.f, acc[nt][2], cn0);
                if (d <= T1) {
                    float de = exact_dist(r1p, cb + ((size_t)(l * KCB + c) << 7), cn0);
                    atomicMin(&exP[rloc + 8], ((unsigned long long)f2mono(de) << 32) | (unsigned)c);
                }
                d = fmaf(-2.f, acc[nt][3], cn1);
                if (d <= T1) {
                    float de = exact_dist(r1p, cb + ((size_t)(l * KCB + c + 1) << 7), cn1);
                    atomicMin(&exP[rloc + 8], ((unsigned long long)f2mono(de) << 32) | (unsigned)(c + 1));
                }
            }
        }
        __syncthreads();

        // ---- residual update + codes ----
        #pragma unroll
        for (int i = 0; i < 8; i++) {
            int idx = tid + i * TPB;                 // 128*32 float4
            int row = idx >> 5, c4 = idx & 31;
            int win = (int)(exP[row] & 0xffu);
            float4 c = __ldg((const float4*)(cb + ((size_t)(l * KCB + win) << 7)) + c4);
            float4* rp = (float4*)(resF + row * RPAD) + c4;
            float4 rv = *rp;
            *rp = make_float4(rv.x - c.x, rv.y - c.y, rv.z - c.z, rv.w - c.w);
        }
        if (write_codes && tid < ROWS)
            out_codes[(row0 + tid) * NLEV + l] = (float)(int)(exP[tid] & 0xffu);
        __syncthreads();
    }

    // ---- recon = x - residual_final ----
    float4* o4 = (float4*)(out_recon + row0 * DIM);
    #pragma unroll
    for (int i = 0; i < 8; i++) {
        int idx = tid + i * TPB;
        int row = idx >> 5, c4 = idx & 31;
        float4 xv = x4[idx];
        float4 rv = ((float4*)(resF + row * RPAD))[c4];
        o4[idx] = make_float4(xv.x - rv.x, xv.y - rv.y, xv.z - rv.z, xv.w - rv.w);
    }
}

// ---------------------------------------------------------------------------
extern "C" void kernel_launch(void* const* d_in, const int* in_sizes, int n_in,
                              void* d_out, int out_size) {
    const float* x  = (const float*)d_in[0];
    const float* cb = (const float*)d_in[1];
    int nx = in_sizes[0];
    int nc = (n_in > 1) ? in_sizes[1] : 0;
    if (nx == NLEV * KCB * DIM && nc != NLEV * KCB * DIM) {
        const float* t = x; x = cb; cb = t;
        int ts = nx; nx = nc; nc = ts;
    }
    const int B = nx / DIM;

    float* out       = (float*)d_out;
    float* out_codes = out + (size_t)B * DIM;
    int write_codes  = (out_size >= B * DIM + B * NLEV) ? 1 : 0;

    rq_prep_kernel<<<(NLEV * KCB * DIM + 255) / 256, 256>>>(cb);

    cudaFuncSetAttribute(rq_main_kernel,
                         cudaFuncAttributeMaxDynamicSharedMemorySize, SM_TOTAL);
    rq_main_kernel<<<B / ROWS, TPB, SM_TOTAL>>>(x, cb, out, out_codes, write_codes);
}